// round 1
// baseline (speedup 1.0000x reference)
#include <cuda_runtime.h>
#include <cstdint>

// Problem constants
#define B_   8
#define N1_  8192
#define N2_  2048
#define C1_  128
#define C2_  256
#define H_   256
#define CIN_ 384   // C2 + C1

// ---------------- device scratch (no allocations allowed) ----------------
__device__ float g_feat2t[B_ * N2_ * C2_];        // 16 MB  [B][N2][C2]
__device__ int   g_idx[B_ * N1_ * 3];
__device__ float g_w  [B_ * N1_ * 3];
__device__ float g_xcat[B_ * CIN_ * N1_];         // 100 MB [B][384][8192]
__device__ float g_y1  [B_ * H_ * N1_];           // 67 MB  [B][256][8192]
__device__ float g_A1[H_ * CIN_];
__device__ float g_c1[H_];
__device__ float g_A2[H_ * H_];
__device__ float g_c2[H_];

// ---------------- 1) transpose features2 [B][C2][N2] -> [B][N2][C2] ------
__global__ void transpose_f2_kernel(const float* __restrict__ f2) {
    __shared__ float tile[32][33];
    int b  = blockIdx.z;
    int c0 = blockIdx.y * 32;
    int n0 = blockIdx.x * 32;
    int tx = threadIdx.x, ty = threadIdx.y;   // 32 x 8
    const float* src = f2 + (size_t)b * C2_ * N2_;
#pragma unroll
    for (int i = 0; i < 32; i += 8)
        tile[ty + i][tx] = src[(size_t)(c0 + ty + i) * N2_ + n0 + tx];
    __syncthreads();
    float* dst = g_feat2t + (size_t)b * N2_ * C2_;
#pragma unroll
    for (int i = 0; i < 32; i += 8)
        dst[(size_t)(n0 + ty + i) * C2_ + c0 + tx] = tile[tx][ty + i];
}

// ---------------- 2) fold BN into conv weights -----------------------------
__global__ void prep_kernel(const float* __restrict__ w, const float* __restrict__ bb,
                            const float* __restrict__ g, const float* __restrict__ be,
                            const float* __restrict__ m, const float* __restrict__ v,
                            int K, int which) {
    float* A = which ? g_A2 : g_A1;
    float* c = which ? g_c2 : g_c1;
    int tid = blockIdx.x * blockDim.x + threadIdx.x;
    if (tid < H_) {
        float s = g[tid] * rsqrtf(v[tid] + 1e-5f);
        c[tid] = (bb[tid] - m[tid]) * s + be[tid];
    }
    int total = H_ * K;
    for (int j = tid; j < total; j += gridDim.x * blockDim.x) {
        int o = j / K;
        float s = g[o] * rsqrtf(v[o] + 1e-5f);
        A[j] = w[j] * s;
    }
}

// ---------------- 3) kNN (k=3) + inverse-distance weights ------------------
__global__ void knn_kernel(const float* __restrict__ xyz1, const float* __restrict__ xyz2) {
    __shared__ float sx[N2_], sy[N2_], sz[N2_];
    int b = blockIdx.y;
    const float* x2 = xyz2 + (size_t)b * 3 * N2_;
    for (int i = threadIdx.x; i < N2_; i += blockDim.x) {
        sx[i] = x2[i];
        sy[i] = x2[N2_ + i];
        sz[i] = x2[2 * N2_ + i];
    }
    __syncthreads();

    int n = blockIdx.x * blockDim.x + threadIdx.x;
    const float* x1 = xyz1 + (size_t)b * 3 * N1_;
    float px = x1[n], py = x1[N1_ + n], pz = x1[2 * N1_ + n];

    float d0 = 3.4e38f, d1 = 3.4e38f, d2 = 3.4e38f;
    int   i0 = 0, i1 = 0, i2 = 0;
    for (int j = 0; j < N2_; j++) {
        float dx = px - sx[j];
        float dy = py - sy[j];
        float dz = pz - sz[j];
        float d = dx * dx + dy * dy + dz * dz;
        if (d < d2) {
            if (d < d1) {
                if (d < d0) { d2 = d1; i2 = i1; d1 = d0; i1 = i0; d0 = d; i0 = j; }
                else        { d2 = d1; i2 = i1; d1 = d;  i1 = j; }
            } else          { d2 = d;  i2 = j; }
        }
    }
    d0 = fmaxf(d0, 1e-10f);
    d1 = fmaxf(d1, 1e-10f);
    d2 = fmaxf(d2, 1e-10f);
    float w0 = 1.0f / d0, w1 = 1.0f / d1, w2 = 1.0f / d2;
    float inv = 1.0f / (w0 + w1 + w2);
    size_t base = ((size_t)b * N1_ + n) * 3;
    g_idx[base + 0] = i0; g_idx[base + 1] = i1; g_idx[base + 2] = i2;
    g_w[base + 0] = w0 * inv; g_w[base + 1] = w1 * inv; g_w[base + 2] = w2 * inv;
}

// ---------------- 4) gather + interpolate -> xcat channels [0,256) ---------
// block: 256 threads, handles 32 points for one batch. Channel-major output.
__global__ void interp_kernel() {
    __shared__ float sh[32][257];
    __shared__ int   sidx[32 * 3];
    __shared__ float sw[32 * 3];
    int b  = blockIdx.y;
    int n0 = blockIdx.x * 32;
    int t  = threadIdx.x;    // == channel for phase 1

    if (t < 96) {
        size_t base = ((size_t)b * N1_ + n0) * 3;
        sidx[t] = g_idx[base + t];
        sw[t]   = g_w[base + t];
    }
    __syncthreads();

    const float* f2 = g_feat2t + (size_t)b * N2_ * C2_;
#pragma unroll 4
    for (int p = 0; p < 32; p++) {
        float acc = sw[p * 3 + 0] * f2[(size_t)sidx[p * 3 + 0] * C2_ + t]
                  + sw[p * 3 + 1] * f2[(size_t)sidx[p * 3 + 1] * C2_ + t]
                  + sw[p * 3 + 2] * f2[(size_t)sidx[p * 3 + 2] * C2_ + t];
        sh[p][t] = acc;
    }
    __syncthreads();

    float* xc = g_xcat + (size_t)b * CIN_ * N1_ + n0;
    int col = t & 31;          // 0..31 point within tile
    int crow = t >> 5;         // 0..7
#pragma unroll
    for (int r = 0; r < 32; r++) {
        int c = r * 8 + crow;
        xc[(size_t)c * N1_ + col] = sh[col][c];
    }
}

// ---------------- 5) copy skip features into xcat channels [256,384) -------
__global__ void copy_skip_kernel(const float* __restrict__ f1) {
    long i = (long)blockIdx.x * blockDim.x + threadIdx.x;  // float4 index
    const long per_b = (long)C1_ * N1_ / 4;                // 262144
    if (i < (long)B_ * per_b) {
        long b = i / per_b, r = i % per_b;
        float4 v = ((const float4*)f1)[b * per_b + r];
        ((float4*)g_xcat)[((long)b * CIN_ + C2_) * (N1_ / 4) + r] = v;
    }
}

// ---------------- 6) SGEMM 256 x K x 8192 per batch, bias + ReLU epilogue --
// C[b][m][n] = relu(sum_k A[m][k] * X[b][k][n] + bias[m])
// 128x128 tile, BK=16, 256 threads, 8x8 per thread, double-buffered SMEM.
template <int K, int LAYER>
__global__ void __launch_bounds__(256, 2)
gemm_bias_relu_kernel(float* __restrict__ out_final) {
    const float* __restrict__ A    = (LAYER == 0) ? g_A1 : g_A2;
    const float* __restrict__ bias = (LAYER == 0) ? g_c1 : g_c2;
    const float* __restrict__ X    = (LAYER == 0) ? g_xcat : g_y1;
    float* __restrict__ Y          = (LAYER == 0) ? g_y1 : out_final;

    constexpr int KT = K / 16;
    __shared__ float As[2][16][128];
    __shared__ float Bs[2][16][128];

    int b  = blockIdx.z;
    int n0 = blockIdx.x * 128;
    int m0 = blockIdx.y * 128;
    const float* Xb = X + (size_t)b * K * N1_;

    int t  = threadIdx.x;
    int tx = t & 15;          // n-dim micro tile
    int ty = t >> 4;          // m-dim micro tile

    int row_a = t >> 2;            // 0..63
    int kc    = (t & 3) << 2;      // 0,4,8,12
    int krow  = t >> 5;            // 0..7
    int nc    = (t & 31) << 2;     // 0..124

    float acc[8][8] = {};
    float4 aA0, aA1, aX0, aX1;

    // prologue: load k-tile 0
    aA0 = *(const float4*)&A[(size_t)(m0 + row_a) * K + kc];
    aA1 = *(const float4*)&A[(size_t)(m0 + row_a + 64) * K + kc];
    aX0 = *(const float4*)&Xb[(size_t)krow * N1_ + n0 + nc];
    aX1 = *(const float4*)&Xb[(size_t)(krow + 8) * N1_ + n0 + nc];
    As[0][kc + 0][row_a]      = aA0.x;
    As[0][kc + 1][row_a]      = aA0.y;
    As[0][kc + 2][row_a]      = aA0.z;
    As[0][kc + 3][row_a]      = aA0.w;
    As[0][kc + 0][row_a + 64] = aA1.x;
    As[0][kc + 1][row_a + 64] = aA1.y;
    As[0][kc + 2][row_a + 64] = aA1.z;
    As[0][kc + 3][row_a + 64] = aA1.w;
    *(float4*)&Bs[0][krow][nc]     = aX0;
    *(float4*)&Bs[0][krow + 8][nc] = aX1;
    __syncthreads();

    int cur = 0;
#pragma unroll 2
    for (int kt = 0; kt < KT; kt++) {
        if (kt + 1 < KT) {
            int k0 = (kt + 1) * 16;
            aA0 = *(const float4*)&A[(size_t)(m0 + row_a) * K + k0 + kc];
            aA1 = *(const float4*)&A[(size_t)(m0 + row_a + 64) * K + k0 + kc];
            aX0 = *(const float4*)&Xb[(size_t)(k0 + krow) * N1_ + n0 + nc];
            aX1 = *(const float4*)&Xb[(size_t)(k0 + krow + 8) * N1_ + n0 + nc];
        }
#pragma unroll
        for (int kk = 0; kk < 16; kk++) {
            float ar[8], br[8];
            *(float4*)&ar[0] = *(const float4*)&As[cur][kk][ty * 8];
            *(float4*)&ar[4] = *(const float4*)&As[cur][kk][ty * 8 + 4];
            *(float4*)&br[0] = *(const float4*)&Bs[cur][kk][tx * 8];
            *(float4*)&br[4] = *(const float4*)&Bs[cur][kk][tx * 8 + 4];
#pragma unroll
            for (int i = 0; i < 8; i++)
#pragma unroll
                for (int j = 0; j < 8; j++)
                    acc[i][j] += ar[i] * br[j];
        }
        if (kt + 1 < KT) {
            int nxt = cur ^ 1;
            As[nxt][kc + 0][row_a]      = aA0.x;
            As[nxt][kc + 1][row_a]      = aA0.y;
            As[nxt][kc + 2][row_a]      = aA0.z;
            As[nxt][kc + 3][row_a]      = aA0.w;
            As[nxt][kc + 0][row_a + 64] = aA1.x;
            As[nxt][kc + 1][row_a + 64] = aA1.y;
            As[nxt][kc + 2][row_a + 64] = aA1.z;
            As[nxt][kc + 3][row_a + 64] = aA1.w;
            *(float4*)&Bs[nxt][krow][nc]     = aX0;
            *(float4*)&Bs[nxt][krow + 8][nc] = aX1;
            __syncthreads();
            cur = nxt;
        }
    }

    // epilogue: bias + relu, vectorized stores
    float* Yb = Y + (size_t)b * H_ * N1_;
#pragma unroll
    for (int i = 0; i < 8; i++) {
        int m = m0 + ty * 8 + i;
        float bv = bias[m];
        float4 v0, v1;
        v0.x = fmaxf(acc[i][0] + bv, 0.0f);
        v0.y = fmaxf(acc[i][1] + bv, 0.0f);
        v0.z = fmaxf(acc[i][2] + bv, 0.0f);
        v0.w = fmaxf(acc[i][3] + bv, 0.0f);
        v1.x = fmaxf(acc[i][4] + bv, 0.0f);
        v1.y = fmaxf(acc[i][5] + bv, 0.0f);
        v1.z = fmaxf(acc[i][6] + bv, 0.0f);
        v1.w = fmaxf(acc[i][7] + bv, 0.0f);
        *(float4*)&Yb[(size_t)m * N1_ + n0 + tx * 8]     = v0;
        *(float4*)&Yb[(size_t)m * N1_ + n0 + tx * 8 + 4] = v1;
    }
}

// ---------------- launch ----------------------------------------------------
extern "C" void kernel_launch(void* const* d_in, const int* in_sizes, int n_in,
                              void* d_out, int out_size) {
    const float* xyz1      = (const float*)d_in[0];
    const float* xyz2      = (const float*)d_in[1];
    const float* features1 = (const float*)d_in[2];
    const float* features2 = (const float*)d_in[3];
    const float* w1 = (const float*)d_in[4];
    const float* b1 = (const float*)d_in[5];
    const float* g1 = (const float*)d_in[6];
    const float* be1 = (const float*)d_in[7];
    const float* m1 = (const float*)d_in[8];
    const float* v1 = (const float*)d_in[9];
    const float* w2 = (const float*)d_in[10];
    const float* b2 = (const float*)d_in[11];
    const float* g2 = (const float*)d_in[12];
    const float* be2 = (const float*)d_in[13];
    const float* m2 = (const float*)d_in[14];
    const float* v2 = (const float*)d_in[15];
    float* out = (float*)d_out;

    transpose_f2_kernel<<<dim3(N2_ / 32, C2_ / 32, B_), dim3(32, 8)>>>(features2);
    prep_kernel<<<96, 256>>>(w1, b1, g1, be1, m1, v1, CIN_, 0);
    prep_kernel<<<96, 256>>>(w2, b2, g2, be2, m2, v2, H_, 1);
    knn_kernel<<<dim3(N1_ / 256, B_), 256>>>(xyz1, xyz2);
    interp_kernel<<<dim3(N1_ / 32, B_), 256>>>();
    {
        long total_f4 = (long)B_ * C1_ * N1_ / 4;
        copy_skip_kernel<<<(unsigned)((total_f4 + 255) / 256), 256>>>(features1);
    }
    gemm_bias_relu_kernel<CIN_, 0><<<dim3(N1_ / 128, 2, B_), 256>>>(nullptr);
    gemm_bias_relu_kernel<H_, 1><<<dim3(N1_ / 128, 2, B_), 256>>>(out);
}

// round 2
// speedup vs baseline: 1.0157x; 1.0157x over previous
#include <cuda_runtime.h>
#include <cstdint>

// Problem constants
#define B_   8
#define N1_  8192
#define N2_  2048
#define C1_  128
#define C2_  256
#define H_   256
#define CIN_ 384   // C2 + C1

typedef unsigned long long u64;

// ---------------- device scratch (no allocations allowed) ----------------
__device__ float g_feat2t[B_ * N2_ * C2_];        // [B][N2][C2]
__device__ int   g_idx[B_ * N1_ * 3];
__device__ float g_w  [B_ * N1_ * 3];
__device__ float g_xcat[B_ * CIN_ * N1_];         // [B][384][8192]
__device__ float g_y1  [B_ * H_ * N1_];           // [B][256][8192]
__device__ float g_A1[H_ * CIN_];
__device__ float g_c1[H_];
__device__ float g_A2[H_ * H_];
__device__ float g_c2[H_];

// ---------------- packed fp32x2 helpers -------------------------------------
__device__ __forceinline__ u64 pack_dup(float x) {
    u64 r;
    asm("mov.b64 %0, {%1, %1};" : "=l"(r) : "f"(x));
    return r;
}
__device__ __forceinline__ void fma2(u64& d, u64 a, u64 b) {
    asm("fma.rn.f32x2 %0, %1, %2, %0;" : "+l"(d) : "l"(a), "l"(b));
}
__device__ __forceinline__ void unpack2(float& lo, float& hi, u64 v) {
    asm("mov.b64 {%0, %1}, %2;" : "=f"(lo), "=f"(hi) : "l"(v));
}

// ---------------- 1) transpose features2 [B][C2][N2] -> [B][N2][C2] ------
__global__ void transpose_f2_kernel(const float* __restrict__ f2) {
    __shared__ float tile[32][33];
    int b  = blockIdx.z;
    int c0 = blockIdx.y * 32;
    int n0 = blockIdx.x * 32;
    int tx = threadIdx.x, ty = threadIdx.y;   // 32 x 8
    const float* src = f2 + (size_t)b * C2_ * N2_;
#pragma unroll
    for (int i = 0; i < 32; i += 8)
        tile[ty + i][tx] = src[(size_t)(c0 + ty + i) * N2_ + n0 + tx];
    __syncthreads();
    float* dst = g_feat2t + (size_t)b * N2_ * C2_;
#pragma unroll
    for (int i = 0; i < 32; i += 8)
        dst[(size_t)(n0 + ty + i) * C2_ + c0 + tx] = tile[tx][ty + i];
}

// ---------------- 2) fold BN into conv weights -----------------------------
__global__ void prep_kernel(const float* __restrict__ w, const float* __restrict__ bb,
                            const float* __restrict__ g, const float* __restrict__ be,
                            const float* __restrict__ m, const float* __restrict__ v,
                            int K, int which) {
    float* A = which ? g_A2 : g_A1;
    float* c = which ? g_c2 : g_c1;
    int tid = blockIdx.x * blockDim.x + threadIdx.x;
    if (tid < H_) {
        float s = g[tid] * rsqrtf(v[tid] + 1e-5f);
        c[tid] = (bb[tid] - m[tid]) * s + be[tid];
    }
    int total = H_ * K;
    for (int j = tid; j < total; j += gridDim.x * blockDim.x) {
        int o = j / K;
        float s = g[o] * rsqrtf(v[o] + 1e-5f);
        A[j] = w[j] * s;
    }
}

// ---------------- 3) kNN (k=3) + inverse-distance weights ------------------
// Uses monotone surrogate d' = |x2|^2 - 2<x1,x2>  (|x1|^2 added to winners).
__global__ void knn_kernel(const float* __restrict__ xyz1, const float* __restrict__ xyz2) {
    __shared__ float sx[N2_], sy[N2_], sz[N2_], sn[N2_];
    int b = blockIdx.y;
    const float* x2 = xyz2 + (size_t)b * 3 * N2_;
    for (int i = threadIdx.x; i < N2_; i += blockDim.x) {
        float X = x2[i];
        float Y = x2[N2_ + i];
        float Z = x2[2 * N2_ + i];
        sx[i] = X; sy[i] = Y; sz[i] = Z;
        sn[i] = X * X + Y * Y + Z * Z;
    }
    __syncthreads();

    int n = blockIdx.x * blockDim.x + threadIdx.x;
    const float* x1 = xyz1 + (size_t)b * 3 * N1_;
    float px = x1[n], py = x1[N1_ + n], pz = x1[2 * N1_ + n];

    float d0 = 3.4e38f, d1 = 3.4e38f, d2 = 3.4e38f;
    int   i0 = 0, i1 = 0, i2 = 0;
#pragma unroll 4
    for (int j = 0; j < N2_; j++) {
        float dot = px * sx[j];
        dot = fmaf(py, sy[j], dot);
        dot = fmaf(pz, sz[j], dot);
        float d = fmaf(-2.0f, dot, sn[j]);
        if (d < d2) {
            if (d < d1) {
                if (d < d0) { d2 = d1; i2 = i1; d1 = d0; i1 = i0; d0 = d; i0 = j; }
                else        { d2 = d1; i2 = i1; d1 = d;  i1 = j; }
            } else          { d2 = d;  i2 = j; }
        }
    }
    float pn = px * px + py * py + pz * pz;
    d0 = fmaxf(d0 + pn, 1e-10f);
    d1 = fmaxf(d1 + pn, 1e-10f);
    d2 = fmaxf(d2 + pn, 1e-10f);
    float w0 = 1.0f / d0, w1 = 1.0f / d1, w2 = 1.0f / d2;
    float inv = 1.0f / (w0 + w1 + w2);
    size_t base = ((size_t)b * N1_ + n) * 3;
    g_idx[base + 0] = i0; g_idx[base + 1] = i1; g_idx[base + 2] = i2;
    g_w[base + 0] = w0 * inv; g_w[base + 1] = w1 * inv; g_w[base + 2] = w2 * inv;
}

// ---------------- 4) gather + interpolate -> xcat channels [0,256) ---------
__global__ void interp_kernel() {
    __shared__ float sh[32][257];
    __shared__ int   sidx[32 * 3];
    __shared__ float sw[32 * 3];
    int b  = blockIdx.y;
    int n0 = blockIdx.x * 32;
    int t  = threadIdx.x;

    if (t < 96) {
        size_t base = ((size_t)b * N1_ + n0) * 3;
        sidx[t] = g_idx[base + t];
        sw[t]   = g_w[base + t];
    }
    __syncthreads();

    const float* f2 = g_feat2t + (size_t)b * N2_ * C2_;
#pragma unroll 4
    for (int p = 0; p < 32; p++) {
        float acc = sw[p * 3 + 0] * f2[(size_t)sidx[p * 3 + 0] * C2_ + t]
                  + sw[p * 3 + 1] * f2[(size_t)sidx[p * 3 + 1] * C2_ + t]
                  + sw[p * 3 + 2] * f2[(size_t)sidx[p * 3 + 2] * C2_ + t];
        sh[p][t] = acc;
    }
    __syncthreads();

    float* xc = g_xcat + (size_t)b * CIN_ * N1_ + n0;
    int col = t & 31;
    int crow = t >> 5;
#pragma unroll
    for (int r = 0; r < 32; r++) {
        int c = r * 8 + crow;
        xc[(size_t)c * N1_ + col] = sh[col][c];
    }
}

// ---------------- 5) copy skip features into xcat channels [256,384) -------
__global__ void copy_skip_kernel(const float* __restrict__ f1) {
    long i = (long)blockIdx.x * blockDim.x + threadIdx.x;
    const long per_b = (long)C1_ * N1_ / 4;
    if (i < (long)B_ * per_b) {
        long b = i / per_b, r = i % per_b;
        float4 v = ((const float4*)f1)[b * per_b + r];
        ((float4*)g_xcat)[((long)b * CIN_ + C2_) * (N1_ / 4) + r] = v;
    }
}

// ---------------- 6) SGEMM with packed fp32x2 (FFMA2) ----------------------
// C[b][m][n] = relu(sum_k A[m][k] * X[b][k][n] + bias[m])
// 128x128 tile, BK=16, 256 threads, 8m x 8n per thread (4 packed n-pairs).
template <int K, int LAYER>
__global__ void __launch_bounds__(256, 2)
gemm_bias_relu_kernel(float* __restrict__ out_final) {
    const float* __restrict__ A    = (LAYER == 0) ? g_A1 : g_A2;
    const float* __restrict__ bias = (LAYER == 0) ? g_c1 : g_c2;
    const float* __restrict__ X    = (LAYER == 0) ? g_xcat : g_y1;
    float* __restrict__ Y          = (LAYER == 0) ? g_y1 : out_final;

    constexpr int KT = K / 16;
    __shared__ float As[2][16][128];
    __shared__ float Bs[2][16][128];

    int b  = blockIdx.z;
    int n0 = blockIdx.x * 128;
    int m0 = blockIdx.y * 128;
    const float* Xb = X + (size_t)b * K * N1_;

    int t  = threadIdx.x;
    int tx = t & 15;          // n-dim micro tile
    int ty = t >> 4;          // m-dim micro tile

    int row_a = t >> 2;            // 0..63
    int kc    = (t & 3) << 2;      // 0,4,8,12
    int krow  = t >> 5;            // 0..7
    int nc    = (t & 31) << 2;     // 0..124

    u64 acc2[8][4];
#pragma unroll
    for (int i = 0; i < 8; i++)
#pragma unroll
        for (int j = 0; j < 4; j++) acc2[i][j] = 0ull;

    float4 aA0, aA1, aX0, aX1;

    // prologue: load k-tile 0
    aA0 = *(const float4*)&A[(size_t)(m0 + row_a) * K + kc];
    aA1 = *(const float4*)&A[(size_t)(m0 + row_a + 64) * K + kc];
    aX0 = *(const float4*)&Xb[(size_t)krow * N1_ + n0 + nc];
    aX1 = *(const float4*)&Xb[(size_t)(krow + 8) * N1_ + n0 + nc];
    As[0][kc + 0][row_a]      = aA0.x;
    As[0][kc + 1][row_a]      = aA0.y;
    As[0][kc + 2][row_a]      = aA0.z;
    As[0][kc + 3][row_a]      = aA0.w;
    As[0][kc + 0][row_a + 64] = aA1.x;
    As[0][kc + 1][row_a + 64] = aA1.y;
    As[0][kc + 2][row_a + 64] = aA1.z;
    As[0][kc + 3][row_a + 64] = aA1.w;
    *(float4*)&Bs[0][krow][nc]     = aX0;
    *(float4*)&Bs[0][krow + 8][nc] = aX1;
    __syncthreads();

    int cur = 0;
#pragma unroll 2
    for (int kt = 0; kt < KT; kt++) {
        if (kt + 1 < KT) {
            int k0 = (kt + 1) * 16;
            aA0 = *(const float4*)&A[(size_t)(m0 + row_a) * K + k0 + kc];
            aA1 = *(const float4*)&A[(size_t)(m0 + row_a + 64) * K + k0 + kc];
            aX0 = *(const float4*)&Xb[(size_t)(k0 + krow) * N1_ + n0 + nc];
            aX1 = *(const float4*)&Xb[(size_t)(k0 + krow + 8) * N1_ + n0 + nc];
        }
#pragma unroll
        for (int kk = 0; kk < 16; kk++) {
            float ar[8];
            *(float4*)&ar[0] = *(const float4*)&As[cur][kk][ty * 8];
            *(float4*)&ar[4] = *(const float4*)&As[cur][kk][ty * 8 + 4];
            // packed n-pairs straight out of shared memory (16B aligned)
            ulonglong2 bq0 = *(const ulonglong2*)&Bs[cur][kk][tx * 8];
            ulonglong2 bq1 = *(const ulonglong2*)&Bs[cur][kk][tx * 8 + 4];
            u64 br2[4] = {bq0.x, bq0.y, bq1.x, bq1.y};
#pragma unroll
            for (int i = 0; i < 8; i++) {
                u64 a2 = pack_dup(ar[i]);
                fma2(acc2[i][0], a2, br2[0]);
                fma2(acc2[i][1], a2, br2[1]);
                fma2(acc2[i][2], a2, br2[2]);
                fma2(acc2[i][3], a2, br2[3]);
            }
        }
        if (kt + 1 < KT) {
            int nxt = cur ^ 1;
            As[nxt][kc + 0][row_a]      = aA0.x;
            As[nxt][kc + 1][row_a]      = aA0.y;
            As[nxt][kc + 2][row_a]      = aA0.z;
            As[nxt][kc + 3][row_a]      = aA0.w;
            As[nxt][kc + 0][row_a + 64] = aA1.x;
            As[nxt][kc + 1][row_a + 64] = aA1.y;
            As[nxt][kc + 2][row_a + 64] = aA1.z;
            As[nxt][kc + 3][row_a + 64] = aA1.w;
            *(float4*)&Bs[nxt][krow][nc]     = aX0;
            *(float4*)&Bs[nxt][krow + 8][nc] = aX1;
            __syncthreads();
            cur = nxt;
        }
    }

    // epilogue: bias + relu, vectorized stores
    float* Yb = Y + (size_t)b * H_ * N1_;
#pragma unroll
    for (int i = 0; i < 8; i++) {
        int m = m0 + ty * 8 + i;
        float bv = bias[m];
        float c0, c1, c2, c3, c4, c5, c6, c7;
        unpack2(c0, c1, acc2[i][0]);
        unpack2(c2, c3, acc2[i][1]);
        unpack2(c4, c5, acc2[i][2]);
        unpack2(c6, c7, acc2[i][3]);
        float4 v0, v1;
        v0.x = fmaxf(c0 + bv, 0.0f);
        v0.y = fmaxf(c1 + bv, 0.0f);
        v0.z = fmaxf(c2 + bv, 0.0f);
        v0.w = fmaxf(c3 + bv, 0.0f);
        v1.x = fmaxf(c4 + bv, 0.0f);
        v1.y = fmaxf(c5 + bv, 0.0f);
        v1.z = fmaxf(c6 + bv, 0.0f);
        v1.w = fmaxf(c7 + bv, 0.0f);
        *(float4*)&Yb[(size_t)m * N1_ + n0 + tx * 8]     = v0;
        *(float4*)&Yb[(size_t)m * N1_ + n0 + tx * 8 + 4] = v1;
    }
}

// ---------------- launch ----------------------------------------------------
extern "C" void kernel_launch(void* const* d_in, const int* in_sizes, int n_in,
                              void* d_out, int out_size) {
    const float* xyz1      = (const float*)d_in[0];
    const float* xyz2      = (const float*)d_in[1];
    const float* features1 = (const float*)d_in[2];
    const float* features2 = (const float*)d_in[3];
    const float* w1 = (const float*)d_in[4];
    const float* b1 = (const float*)d_in[5];
    const float* g1 = (const float*)d_in[6];
    const float* be1 = (const float*)d_in[7];
    const float* m1 = (const float*)d_in[8];
    const float* v1 = (const float*)d_in[9];
    const float* w2 = (const float*)d_in[10];
    const float* b2 = (const float*)d_in[11];
    const float* g2 = (const float*)d_in[12];
    const float* be2 = (const float*)d_in[13];
    const float* m2 = (const float*)d_in[14];
    const float* v2 = (const float*)d_in[15];
    float* out = (float*)d_out;

    transpose_f2_kernel<<<dim3(N2_ / 32, C2_ / 32, B_), dim3(32, 8)>>>(features2);
    prep_kernel<<<96, 256>>>(w1, b1, g1, be1, m1, v1, CIN_, 0);
    prep_kernel<<<96, 256>>>(w2, b2, g2, be2, m2, v2, H_, 1);
    knn_kernel<<<dim3(N1_ / 256, B_), 256>>>(xyz1, xyz2);
    interp_kernel<<<dim3(N1_ / 32, B_), 256>>>();
    {
        long total_f4 = (long)B_ * C1_ * N1_ / 4;
        copy_skip_kernel<<<(unsigned)((total_f4 + 255) / 256), 256>>>(features1);
    }
    gemm_bias_relu_kernel<CIN_, 0><<<dim3(N1_ / 128, 2, B_), 256>>>(nullptr);
    gemm_bias_relu_kernel<H_, 1><<<dim3(N1_ / 128, 2, B_), 256>>>(out);
}

// round 4
// speedup vs baseline: 1.5620x; 1.5379x over previous
#include <cuda_runtime.h>
#include <cstdint>

// Problem constants
#define B_   8
#define N1_  8192
#define N2_  2048
#define C1_  128
#define C2_  256
#define H_   256
#define CIN_ 384   // C2 + C1

typedef unsigned long long u64;

// ---------------- device scratch (no allocations allowed) ----------------
__device__ float  g_feat2t[B_ * N2_ * C2_];     // [B][N2][C2] fp32
__device__ float4 g_x2p[B_ * N2_];              // packed {x,y,z,|x|^2}
__device__ int    g_idx[B_ * N1_ * 3];
__device__ float  g_w  [B_ * N1_ * 3];
__device__ float  g_pd [B_ * N1_ * 4 * 3];      // partial top-3 dists (4 quarters)
__device__ int    g_pi [B_ * N1_ * 4 * 3];      // partial top-3 indices
__device__ float  g_xcat[B_ * N1_ * CIN_];      // [B][N1][384] tf32-rounded
__device__ float  g_y1  [B_ * N1_ * H_];        // [B][N1][256] tf32-rounded
__device__ float  g_A1[H_ * CIN_];              // tf32-rounded folded weights
__device__ float  g_c1[H_];
__device__ float  g_A2[H_ * H_];
__device__ float  g_c2[H_];

// ---------------- small PTX helpers ----------------------------------------
__device__ __forceinline__ float to_tf32(float x) {
    unsigned u;
    asm("cvt.rna.tf32.f32 %0, %1;" : "=r"(u) : "f"(x));
    return __uint_as_float(u);
}
__device__ __forceinline__ uint32_t smem_u32(const void* p) {
    uint32_t a;
    asm("{ .reg .u64 t; cvta.to.shared.u64 t, %1; cvt.u32.u64 %0, t; }" : "=r"(a) : "l"(p));
    return a;
}
__device__ __forceinline__ void cpa16(uint32_t dst, const float* src) {
    asm volatile("cp.async.cg.shared.global [%0], [%1], 16;" :: "r"(dst), "l"(src));
}
#define CP_COMMIT()  asm volatile("cp.async.commit_group;")
#define CP_WAIT1()   asm volatile("cp.async.wait_group 1;")
#define CP_WAIT0()   asm volatile("cp.async.wait_group 0;")

// m16n8k8 tf32 MMA, D = A*B + D
__device__ __forceinline__ void mma_tf32(float* c, const uint32_t* a,
                                         uint32_t b0, uint32_t b1) {
    asm volatile(
        "mma.sync.aligned.m16n8k8.row.col.f32.tf32.tf32.f32 "
        "{%0,%1,%2,%3}, {%4,%5,%6,%7}, {%8,%9}, {%0,%1,%2,%3};"
        : "+f"(c[0]), "+f"(c[1]), "+f"(c[2]), "+f"(c[3])
        : "r"(a[0]), "r"(a[1]), "r"(a[2]), "r"(a[3]), "r"(b0), "r"(b1));
}

// ---------------- 1) transpose features2 [B][C2][N2] -> [B][N2][C2] --------
__global__ void transpose_f2_kernel(const float* __restrict__ f2) {
    __shared__ float tile[32][33];
    int b  = blockIdx.z;
    int c0 = blockIdx.y * 32;
    int n0 = blockIdx.x * 32;
    int tx = threadIdx.x, ty = threadIdx.y;
    const float* src = f2 + (size_t)b * C2_ * N2_;
#pragma unroll
    for (int i = 0; i < 32; i += 8)
        tile[ty + i][tx] = src[(size_t)(c0 + ty + i) * N2_ + n0 + tx];
    __syncthreads();
    float* dst = g_feat2t + (size_t)b * N2_ * C2_;
#pragma unroll
    for (int i = 0; i < 32; i += 8)
        dst[(size_t)(n0 + ty + i) * C2_ + c0 + tx] = tile[tx][ty + i];
}

// ---------------- 2) pack xyz2 into float4 {x,y,z,|x|^2} -------------------
__global__ void pack_x2_kernel(const float* __restrict__ xyz2) {
    int b = blockIdx.y;
    int i = blockIdx.x * 256 + threadIdx.x;
    const float* x2 = xyz2 + (size_t)b * 3 * N2_;
    float X = x2[i], Y = x2[N2_ + i], Z = x2[2 * N2_ + i];
    g_x2p[b * N2_ + i] = make_float4(X, Y, Z, X * X + Y * Y + Z * Z);
}

// ---------------- 3) fold BN into conv weights (tf32-rounded) --------------
__global__ void prep_kernel(const float* __restrict__ w, const float* __restrict__ bb,
                            const float* __restrict__ g, const float* __restrict__ be,
                            const float* __restrict__ m, const float* __restrict__ v,
                            int K, int which) {
    float* A = which ? g_A2 : g_A1;
    float* c = which ? g_c2 : g_c1;
    int tid = blockIdx.x * blockDim.x + threadIdx.x;
    if (tid < H_) {
        float s = g[tid] * rsqrtf(v[tid] + 1e-5f);
        c[tid] = (bb[tid] - m[tid]) * s + be[tid];
    }
    int total = H_ * K;
    for (int j = tid; j < total; j += gridDim.x * blockDim.x) {
        int o = j / K;
        float s = g[o] * rsqrtf(v[o] + 1e-5f);
        A[j] = to_tf32(w[j] * s);
    }
}

// ---------------- 4) kNN partial: quarter of N2, 2 points/thread -----------
#define QN_ (N2_ / 4)   // 512
__global__ void __launch_bounds__(128)
knn_part_kernel(const float* __restrict__ xyz1) {
    __shared__ float4 s2[QN_];
    int b  = blockIdx.z;
    int q  = blockIdx.y;
    int n0 = blockIdx.x * 256;
    int t  = threadIdx.x;

    const float4* src = g_x2p + b * N2_ + q * QN_;
    for (int i = t; i < QN_; i += 128) s2[i] = src[i];
    __syncthreads();

    const float* x1 = xyz1 + (size_t)b * 3 * N1_;
    int na = n0 + t, nb = n0 + 128 + t;
    float ax = x1[na], ay = x1[N1_ + na], az = x1[2 * N1_ + na];
    float bx = x1[nb], by = x1[N1_ + nb], bz = x1[2 * N1_ + nb];

    float ad0 = 3.4e38f, ad1 = 3.4e38f, ad2 = 3.4e38f;
    float bd0 = 3.4e38f, bd1 = 3.4e38f, bd2 = 3.4e38f;
    int ai0 = 0, ai1 = 0, ai2 = 0, bi0 = 0, bi1 = 0, bi2 = 0;

#pragma unroll 4
    for (int j = 0; j < QN_; j++) {
        float4 p = s2[j];
        float ta = ax * p.x; ta = fmaf(ay, p.y, ta); ta = fmaf(az, p.z, ta);
        float da = fmaf(-2.0f, ta, p.w);
        float tb = bx * p.x; tb = fmaf(by, p.y, tb); tb = fmaf(bz, p.z, tb);
        float db = fmaf(-2.0f, tb, p.w);
        if (da < ad2) {
            if (da < ad1) {
                if (da < ad0) { ad2 = ad1; ai2 = ai1; ad1 = ad0; ai1 = ai0; ad0 = da; ai0 = j; }
                else          { ad2 = ad1; ai2 = ai1; ad1 = da;  ai1 = j; }
            } else            { ad2 = da;  ai2 = j; }
        }
        if (db < bd2) {
            if (db < bd1) {
                if (db < bd0) { bd2 = bd1; bi2 = bi1; bd1 = bd0; bi1 = bi0; bd0 = db; bi0 = j; }
                else          { bd2 = bd1; bi2 = bi1; bd1 = db;  bi1 = j; }
            } else            { bd2 = db;  bi2 = j; }
        }
    }
    int joff = q * QN_;
    size_t basea = ((size_t)(b * N1_ + na) * 4 + q) * 3;
    g_pd[basea + 0] = ad0; g_pd[basea + 1] = ad1; g_pd[basea + 2] = ad2;
    g_pi[basea + 0] = ai0 + joff; g_pi[basea + 1] = ai1 + joff; g_pi[basea + 2] = ai2 + joff;
    size_t baseb = ((size_t)(b * N1_ + nb) * 4 + q) * 3;
    g_pd[baseb + 0] = bd0; g_pd[baseb + 1] = bd1; g_pd[baseb + 2] = bd2;
    g_pi[baseb + 0] = bi0 + joff; g_pi[baseb + 1] = bi1 + joff; g_pi[baseb + 2] = bi2 + joff;
}

// ---------------- 5) merge 4 partial top-3 lists + weights -----------------
__global__ void knn_merge_kernel(const float* __restrict__ xyz1) {
    int gid = blockIdx.x * 256 + threadIdx.x;   // 0 .. B*N1-1
    int b = gid >> 13;
    int n = gid & (N1_ - 1);

    float d0 = 3.4e38f, d1 = 3.4e38f, d2 = 3.4e38f;
    int   i0 = 0, i1 = 0, i2 = 0;
    size_t base = (size_t)gid * 12;
#pragma unroll
    for (int k = 0; k < 12; k++) {
        float d = g_pd[base + k];
        int   i = g_pi[base + k];
        if (d < d2) {
            if (d < d1) {
                if (d < d0) { d2 = d1; i2 = i1; d1 = d0; i1 = i0; d0 = d; i0 = i; }
                else        { d2 = d1; i2 = i1; d1 = d;  i1 = i; }
            } else          { d2 = d;  i2 = i; }
        }
    }
    const float* x1 = xyz1 + (size_t)b * 3 * N1_;
    float px = x1[n], py = x1[N1_ + n], pz = x1[2 * N1_ + n];
    float pn = px * px + py * py + pz * pz;
    d0 = fmaxf(d0 + pn, 1e-10f);
    d1 = fmaxf(d1 + pn, 1e-10f);
    d2 = fmaxf(d2 + pn, 1e-10f);
    float w0 = 1.0f / d0, w1 = 1.0f / d1, w2 = 1.0f / d2;
    float inv = 1.0f / (w0 + w1 + w2);
    size_t ob = (size_t)gid * 3;
    g_idx[ob + 0] = i0; g_idx[ob + 1] = i1; g_idx[ob + 2] = i2;
    g_w[ob + 0] = w0 * inv; g_w[ob + 1] = w1 * inv; g_w[ob + 2] = w2 * inv;
}

// ---------------- 6) gather + interpolate -> xcat[b][n][0..256) ------------
__global__ void interp_kernel() {
    __shared__ int   sidx[16 * 3];
    __shared__ float swt [16 * 3];
    int b  = blockIdx.y;
    int n0 = blockIdx.x * 16;
    int t  = threadIdx.x;          // channel
    if (t < 48) {
        size_t base = ((size_t)(b * N1_ + n0)) * 3;
        sidx[t] = g_idx[base + t];
        swt[t]  = g_w[base + t];
    }
    __syncthreads();
    const float* f2 = g_feat2t + (size_t)b * N2_ * C2_;
    float* xc = g_xcat + ((size_t)(b * N1_ + n0)) * CIN_ + t;
#pragma unroll 4
    for (int p = 0; p < 16; p++) {
        float acc = swt[p * 3 + 0] * f2[(size_t)sidx[p * 3 + 0] * C2_ + t]
                  + swt[p * 3 + 1] * f2[(size_t)sidx[p * 3 + 1] * C2_ + t]
                  + swt[p * 3 + 2] * f2[(size_t)sidx[p * 3 + 2] * C2_ + t];
        xc[(size_t)p * CIN_] = to_tf32(acc);
    }
}

// ---------------- 7) skip features transpose -> xcat[b][n][256..384) -------
__global__ void skip_t_kernel(const float* __restrict__ f1) {
    __shared__ float tile[32][33];
    int b  = blockIdx.z;
    int c0 = blockIdx.y * 32;
    int n0 = blockIdx.x * 32;
    int tx = threadIdx.x, ty = threadIdx.y;
    const float* src = f1 + (size_t)b * C1_ * N1_;
#pragma unroll
    for (int i = 0; i < 32; i += 8)
        tile[ty + i][tx] = src[(size_t)(c0 + ty + i) * N1_ + n0 + tx];
    __syncthreads();
    float* dst = g_xcat + (size_t)b * N1_ * CIN_;
#pragma unroll
    for (int i = 0; i < 32; i += 8)
        dst[(size_t)(n0 + ty + i) * CIN_ + C2_ + c0 + tx] = to_tf32(tile[tx][ty + i]);
}

// ---------------- 8) mma.sync tf32 GEMM + bias + ReLU ----------------------
// Block tile: 128 (M=points) x 256 (N=out ch), BK=16. 8 warps: 2(M) x 4(N),
// warp tile 64x32... (WM=64, WN=64). SMEM holds fragments pre-arranged:
//   A_frag[8 mtiles][2 ksteps][4 regs][32 lanes]   (8 KB)
//   B_frag[32 ntiles][2 ksteps][2 regs][32 lanes]  (16 KB)
// double-buffered -> 48 KB dynamic exactly (no opt-in attr needed).
// LAYER 0: X=g_xcat (K=384) -> g_y1 [b][n][256] (tf32-rounded, relu)
// LAYER 1: X=g_y1   (K=256) -> out  [b][ch][n1] (fp32, relu, coalesced)
#define BUF_FLOATS 6144   // 2048 (A) + 4096 (B) floats per buffer

template <int K, int LAYER>
__global__ void __launch_bounds__(256)
gemm_mma_kernel(float* __restrict__ out_final) {
    constexpr int KT = K / 16;
    extern __shared__ float smem[];     // 2 * 6144 floats = 48 KB
    uint32_t sbase = smem_u32(smem);

    int tid  = threadIdx.x;
    int wid  = tid >> 5;
    int lane = tid & 31;
    int g    = lane >> 2;        // groupID 0..7
    int t4   = lane & 3;         // threadID_in_group

    int wm = wid & 1;            // 0..1  (M warps)
    int wn = wid >> 1;           // 0..3  (N warps)

    int bz = blockIdx.x >> 6;
    int m0 = (blockIdx.x & 63) * 128;

    const float* __restrict__ X  = (LAYER == 0) ? g_xcat : g_y1;
    const float* __restrict__ W  = (LAYER == 0) ? g_A1 : g_A2;
    const float* __restrict__ bi = (LAYER == 0) ? g_c1 : g_c2;
    const float* Abase = X + ((size_t)(bz * N1_ + m0)) * K;

    float acc[4][8][4] = {};

    // ---- staging: fragment-ordered cp.async ----
    // A: 512 16B-chunks (m 0..127, c4 0..3), thread does 2.
    // B: 1024 chunks (n 0..255, c4 0..3), thread does 4.
#define STAGE(buf, kt) do {                                                    \
    uint32_t dbase = sbase + (buf) * (BUF_FLOATS * 4);                         \
    _Pragma("unroll")                                                          \
    for (int c = 0; c < 2; c++) {                                              \
        int id = tid + c * 256;                                                \
        int m = id >> 2, c4 = id & 3;                                          \
        int r = m & 15;                                                        \
        int off = (((m >> 4) * 2 + (c4 >> 1)) * 4 + 2 * (c4 & 1) + (r >> 3)) * 32 \
                  + (r & 7) * 4;                                               \
        cpa16(dbase + off * 4, Abase + (size_t)m * K + (kt) * 16 + c4 * 4);    \
    }                                                                          \
    _Pragma("unroll")                                                          \
    for (int c = 0; c < 4; c++) {                                              \
        int id = tid + c * 256;                                                \
        int n = id >> 2, c4 = id & 3;                                          \
        int off = 2048 + (((n >> 3) * 2 + (c4 >> 1)) * 2 + (c4 & 1)) * 32      \
                  + (n & 7) * 4;                                               \
        cpa16(dbase + off * 4, W + (size_t)n * K + (kt) * 16 + c4 * 4);        \
    }                                                                          \
    CP_COMMIT();                                                               \
} while (0)

    STAGE(0, 0);

#pragma unroll 1
    for (int kt = 0; kt < KT; kt++) {
        int cur = kt & 1;
        if (kt + 1 < KT) { STAGE(cur ^ 1, kt + 1); CP_WAIT1(); }
        else             { CP_WAIT0(); }
        __syncthreads();

        const float* As = smem + cur * BUF_FLOATS;
        const float* Bs = As + 2048;
#pragma unroll
        for (int ks = 0; ks < 2; ks++) {
            uint32_t a[4][4];
#pragma unroll
            for (int mi = 0; mi < 4; mi++) {
                const float* ap = As + (((wm * 4 + mi) * 2 + ks) * 4) * 32 + lane;
                a[mi][0] = __float_as_uint(ap[0]);
                a[mi][1] = __float_as_uint(ap[32]);
                a[mi][2] = __float_as_uint(ap[64]);
                a[mi][3] = __float_as_uint(ap[96]);
            }
#pragma unroll
            for (int ni = 0; ni < 8; ni++) {
                const float* bp = Bs + (((wn * 8 + ni) * 2 + ks) * 2) * 32 + lane;
                uint32_t b0 = __float_as_uint(bp[0]);
                uint32_t b1 = __float_as_uint(bp[32]);
#pragma unroll
                for (int mi = 0; mi < 4; mi++)
                    mma_tf32(acc[mi][ni], a[mi], b0, b1);
            }
        }
        __syncthreads();   // all reads of 'cur' done before it is re-staged
    }

    // ---- epilogue: bias + relu ----
#pragma unroll
    for (int ni = 0; ni < 8; ni++) {
        int n = wn * 64 + ni * 8 + 2 * t4;
        float bv0 = __ldg(&bi[n]);
        float bv1 = __ldg(&bi[n + 1]);
#pragma unroll
        for (int mi = 0; mi < 4; mi++) {
            int m = m0 + wm * 64 + mi * 16 + g;
            float c0 = fmaxf(acc[mi][ni][0] + bv0, 0.0f);
            float c1 = fmaxf(acc[mi][ni][1] + bv1, 0.0f);
            float c2 = fmaxf(acc[mi][ni][2] + bv0, 0.0f);
            float c3 = fmaxf(acc[mi][ni][3] + bv1, 0.0f);
            if (LAYER == 0) {
                float2 v0 = make_float2(to_tf32(c0), to_tf32(c1));
                float2 v1 = make_float2(to_tf32(c2), to_tf32(c3));
                *(float2*)&g_y1[((size_t)(bz * N1_ + m)) * H_ + n]       = v0;
                *(float2*)&g_y1[((size_t)(bz * N1_ + m + 8)) * H_ + n]   = v1;
            } else {
                float* dst = out_final + (size_t)bz * H_ * N1_;
                dst[(size_t)n * N1_ + m]           = c0;
                dst[(size_t)(n + 1) * N1_ + m]     = c1;
                dst[(size_t)n * N1_ + m + 8]       = c2;
                dst[(size_t)(n + 1) * N1_ + m + 8] = c3;
            }
        }
    }
}

// ---------------- launch ----------------------------------------------------
extern "C" void kernel_launch(void* const* d_in, const int* in_sizes, int n_in,
                              void* d_out, int out_size) {
    const float* xyz1      = (const float*)d_in[0];
    const float* xyz2      = (const float*)d_in[1];
    const float* features1 = (const float*)d_in[2];
    const float* features2 = (const float*)d_in[3];
    const float* w1 = (const float*)d_in[4];
    const float* b1 = (const float*)d_in[5];
    const float* g1 = (const float*)d_in[6];
    const float* be1 = (const float*)d_in[7];
    const float* m1 = (const float*)d_in[8];
    const float* v1 = (const float*)d_in[9];
    const float* w2 = (const float*)d_in[10];
    const float* b2 = (const float*)d_in[11];
    const float* g2 = (const float*)d_in[12];
    const float* be2 = (const float*)d_in[13];
    const float* m2 = (const float*)d_in[14];
    const float* v2 = (const float*)d_in[15];
    float* out = (float*)d_out;

    transpose_f2_kernel<<<dim3(N2_ / 32, C2_ / 32, B_), dim3(32, 8)>>>(features2);
    pack_x2_kernel<<<dim3(N2_ / 256, B_), 256>>>(xyz2);
    prep_kernel<<<96, 256>>>(w1, b1, g1, be1, m1, v1, CIN_, 0);
    prep_kernel<<<96, 256>>>(w2, b2, g2, be2, m2, v2, H_, 1);
    knn_part_kernel<<<dim3(N1_ / 256, 4, B_), 128>>>(xyz1);
    knn_merge_kernel<<<(B_ * N1_) / 256, 256>>>(xyz1);
    interp_kernel<<<dim3(N1_ / 16, B_), 256>>>();
    skip_t_kernel<<<dim3(N1_ / 32, C1_ / 32, B_), dim3(32, 8)>>>(features1);
    gemm_mma_kernel<CIN_, 0><<<512, 256, 49152>>>(nullptr);
    gemm_mma_kernel<H_, 1><<<512, 256, 49152>>>(out);
}

// round 5
// speedup vs baseline: 1.6855x; 1.0791x over previous
#include <cuda_runtime.h>
#include <cstdint>

// Problem constants
#define B_   8
#define N1_  8192
#define N2_  2048
#define C1_  128
#define C2_  256
#define H_   256
#define CIN_ 384   // C2 + C1

typedef unsigned long long u64;

// ---------------- device scratch (no allocations allowed) ----------------
__device__ float  g_feat2t[B_ * N2_ * C2_];     // [B][N2][C2] fp32
__device__ float4 g_x2p[B_ * N2_];              // packed {x,y,z,|x|^2}
__device__ int    g_idx[B_ * N1_ * 3];
__device__ float  g_w  [B_ * N1_ * 3];
__device__ float  g_pd [B_ * N1_ * 4 * 3];      // partial top-3 dists (4 quarters)
__device__ int    g_pi [B_ * N1_ * 4 * 3];      // partial top-3 indices
__device__ float  g_xcat[B_ * N1_ * CIN_];      // [B][N1][384] tf32-rounded
__device__ float  g_A1[H_ * CIN_];              // tf32-rounded folded weights
__device__ float  g_c1[H_];
__device__ float  g_A2[H_ * H_];
__device__ float  g_c2[H_];

// ---------------- small PTX helpers ----------------------------------------
__device__ __forceinline__ float to_tf32(float x) {
    unsigned u;
    asm("cvt.rna.tf32.f32 %0, %1;" : "=r"(u) : "f"(x));
    return __uint_as_float(u);
}
__device__ __forceinline__ uint32_t smem_u32(const void* p) {
    uint32_t a;
    asm("{ .reg .u64 t; cvta.to.shared.u64 t, %1; cvt.u32.u64 %0, t; }" : "=r"(a) : "l"(p));
    return a;
}
__device__ __forceinline__ void cpa16(uint32_t dst, const float* src) {
    asm volatile("cp.async.cg.shared.global [%0], [%1], 16;" :: "r"(dst), "l"(src));
}
#define CP_COMMIT()  asm volatile("cp.async.commit_group;")
#define CP_WAIT1()   asm volatile("cp.async.wait_group 1;")
#define CP_WAIT0()   asm volatile("cp.async.wait_group 0;")

// m16n8k8 tf32 MMA, D = A*B + D
__device__ __forceinline__ void mma_tf32(float* c, const uint32_t* a,
                                         uint32_t b0, uint32_t b1) {
    asm volatile(
        "mma.sync.aligned.m16n8k8.row.col.f32.tf32.tf32.f32 "
        "{%0,%1,%2,%3}, {%4,%5,%6,%7}, {%8,%9}, {%0,%1,%2,%3};"
        : "+f"(c[0]), "+f"(c[1]), "+f"(c[2]), "+f"(c[3])
        : "r"(a[0]), "r"(a[1]), "r"(a[2]), "r"(a[3]), "r"(b0), "r"(b1));
}

// ---------------- 1) transpose features2 [B][C2][N2] -> [B][N2][C2] --------
__global__ void transpose_f2_kernel(const float* __restrict__ f2) {
    __shared__ float tile[32][33];
    int b  = blockIdx.z;
    int c0 = blockIdx.y * 32;
    int n0 = blockIdx.x * 32;
    int tx = threadIdx.x, ty = threadIdx.y;
    const float* src = f2 + (size_t)b * C2_ * N2_;
#pragma unroll
    for (int i = 0; i < 32; i += 8)
        tile[ty + i][tx] = src[(size_t)(c0 + ty + i) * N2_ + n0 + tx];
    __syncthreads();
    float* dst = g_feat2t + (size_t)b * N2_ * C2_;
#pragma unroll
    for (int i = 0; i < 32; i += 8)
        dst[(size_t)(n0 + ty + i) * C2_ + c0 + tx] = tile[tx][ty + i];
}

// ---------------- 2) setup: pack xyz2 + fold BN into weights ---------------
__global__ void setup_kernel(const float* __restrict__ xyz2,
                             const float* __restrict__ w1, const float* __restrict__ b1,
                             const float* __restrict__ g1, const float* __restrict__ be1,
                             const float* __restrict__ m1, const float* __restrict__ v1,
                             const float* __restrict__ w2, const float* __restrict__ b2,
                             const float* __restrict__ g2, const float* __restrict__ be2,
                             const float* __restrict__ m2, const float* __restrict__ v2) {
    int blk = blockIdx.x;
    int t = threadIdx.x;
    if (blk < 64) {                       // pack xyz2
        int b = blk >> 3;
        int i = (blk & 7) * 256 + t;
        const float* x2 = xyz2 + (size_t)b * 3 * N2_;
        float X = x2[i], Y = x2[N2_ + i], Z = x2[2 * N2_ + i];
        g_x2p[b * N2_ + i] = make_float4(X, Y, Z, X * X + Y * Y + Z * Z);
    } else {                              // fold BN (32 blocks, 8192 threads)
        int tid2 = (blk - 64) * 256 + t;
        if (tid2 < H_) {
            float s1 = g1[tid2] * rsqrtf(v1[tid2] + 1e-5f);
            g_c1[tid2] = (b1[tid2] - m1[tid2]) * s1 + be1[tid2];
            float s2 = g2[tid2] * rsqrtf(v2[tid2] + 1e-5f);
            g_c2[tid2] = (b2[tid2] - m2[tid2]) * s2 + be2[tid2];
        }
        for (int j = tid2; j < H_ * CIN_; j += 8192) {
            int o = j / CIN_;
            float s = g1[o] * rsqrtf(v1[o] + 1e-5f);
            g_A1[j] = to_tf32(w1[j] * s);
        }
        for (int j = tid2; j < H_ * H_; j += 8192) {
            int o = j / H_;
            float s = g2[o] * rsqrtf(v2[o] + 1e-5f);
            g_A2[j] = to_tf32(w2[j] * s);
        }
    }
}

// ---------------- 3) kNN partial: quarter of N2, 2 points/thread -----------
#define QN_ (N2_ / 4)   // 512
__global__ void __launch_bounds__(128)
knn_part_kernel(const float* __restrict__ xyz1) {
    __shared__ float4 s2[QN_];
    int b  = blockIdx.z;
    int q  = blockIdx.y;
    int n0 = blockIdx.x * 256;
    int t  = threadIdx.x;

    const float4* src = g_x2p + b * N2_ + q * QN_;
    for (int i = t; i < QN_; i += 128) s2[i] = src[i];
    __syncthreads();

    const float* x1 = xyz1 + (size_t)b * 3 * N1_;
    int na = n0 + t, nb = n0 + 128 + t;
    float ax = x1[na], ay = x1[N1_ + na], az = x1[2 * N1_ + na];
    float bx = x1[nb], by = x1[N1_ + nb], bz = x1[2 * N1_ + nb];

    float ad0 = 3.4e38f, ad1 = 3.4e38f, ad2 = 3.4e38f;
    float bd0 = 3.4e38f, bd1 = 3.4e38f, bd2 = 3.4e38f;
    int ai0 = 0, ai1 = 0, ai2 = 0, bi0 = 0, bi1 = 0, bi2 = 0;

#pragma unroll 4
    for (int j = 0; j < QN_; j++) {
        float4 p = s2[j];
        float ta = ax * p.x; ta = fmaf(ay, p.y, ta); ta = fmaf(az, p.z, ta);
        float da = fmaf(-2.0f, ta, p.w);
        float tb = bx * p.x; tb = fmaf(by, p.y, tb); tb = fmaf(bz, p.z, tb);
        float db = fmaf(-2.0f, tb, p.w);
        if (da < ad2) {
            if (da < ad1) {
                if (da < ad0) { ad2 = ad1; ai2 = ai1; ad1 = ad0; ai1 = ai0; ad0 = da; ai0 = j; }
                else          { ad2 = ad1; ai2 = ai1; ad1 = da;  ai1 = j; }
            } else            { ad2 = da;  ai2 = j; }
        }
        if (db < bd2) {
            if (db < bd1) {
                if (db < bd0) { bd2 = bd1; bi2 = bi1; bd1 = bd0; bi1 = bi0; bd0 = db; bi0 = j; }
                else          { bd2 = bd1; bi2 = bi1; bd1 = db;  bi1 = j; }
            } else            { bd2 = db;  bi2 = j; }
        }
    }
    int joff = q * QN_;
    size_t basea = ((size_t)(b * N1_ + na) * 4 + q) * 3;
    g_pd[basea + 0] = ad0; g_pd[basea + 1] = ad1; g_pd[basea + 2] = ad2;
    g_pi[basea + 0] = ai0 + joff; g_pi[basea + 1] = ai1 + joff; g_pi[basea + 2] = ai2 + joff;
    size_t baseb = ((size_t)(b * N1_ + nb) * 4 + q) * 3;
    g_pd[baseb + 0] = bd0; g_pd[baseb + 1] = bd1; g_pd[baseb + 2] = bd2;
    g_pi[baseb + 0] = bi0 + joff; g_pi[baseb + 1] = bi1 + joff; g_pi[baseb + 2] = bi2 + joff;
}

// ---------------- 4) merge 4 partial top-3 lists + weights -----------------
__global__ void knn_merge_kernel(const float* __restrict__ xyz1) {
    int gid = blockIdx.x * 256 + threadIdx.x;   // 0 .. B*N1-1
    int b = gid >> 13;
    int n = gid & (N1_ - 1);

    float d0 = 3.4e38f, d1 = 3.4e38f, d2 = 3.4e38f;
    int   i0 = 0, i1 = 0, i2 = 0;
    size_t base = (size_t)gid * 12;
#pragma unroll
    for (int k = 0; k < 12; k++) {
        float d = g_pd[base + k];
        int   i = g_pi[base + k];
        if (d < d2) {
            if (d < d1) {
                if (d < d0) { d2 = d1; i2 = i1; d1 = d0; i1 = i0; d0 = d; i0 = i; }
                else        { d2 = d1; i2 = i1; d1 = d;  i1 = i; }
            } else          { d2 = d;  i2 = i; }
        }
    }
    const float* x1 = xyz1 + (size_t)b * 3 * N1_;
    float px = x1[n], py = x1[N1_ + n], pz = x1[2 * N1_ + n];
    float pn = px * px + py * py + pz * pz;
    d0 = fmaxf(d0 + pn, 1e-10f);
    d1 = fmaxf(d1 + pn, 1e-10f);
    d2 = fmaxf(d2 + pn, 1e-10f);
    float w0 = 1.0f / d0, w1 = 1.0f / d1, w2 = 1.0f / d2;
    float inv = 1.0f / (w0 + w1 + w2);
    size_t ob = (size_t)gid * 3;
    g_idx[ob + 0] = i0; g_idx[ob + 1] = i1; g_idx[ob + 2] = i2;
    g_w[ob + 0] = w0 * inv; g_w[ob + 1] = w1 * inv; g_w[ob + 2] = w2 * inv;
}

// ---------------- 5) interp (ch 0..255) + skip transpose (ch 256..383) -----
__global__ void interp_skip_kernel(const float* __restrict__ f1) {
    __shared__ int   sidx[16 * 3];
    __shared__ float swt [16 * 3];
    __shared__ float tile[32][33];
    int blk = blockIdx.x;
    int t = threadIdx.x;
    if (blk < 4096) {
        // interp: 16 points per block, thread = channel
        int b  = blk >> 9;
        int n0 = (blk & 511) * 16;
        if (t < 48) {
            size_t base = ((size_t)(b * N1_ + n0)) * 3;
            sidx[t] = g_idx[base + t];
            swt[t]  = g_w[base + t];
        }
        __syncthreads();
        const float* f2 = g_feat2t + (size_t)b * N2_ * C2_;
        float* xc = g_xcat + ((size_t)(b * N1_ + n0)) * CIN_ + t;
#pragma unroll 4
        for (int p = 0; p < 16; p++) {
            float acc = swt[p * 3 + 0] * f2[(size_t)sidx[p * 3 + 0] * C2_ + t]
                      + swt[p * 3 + 1] * f2[(size_t)sidx[p * 3 + 1] * C2_ + t]
                      + swt[p * 3 + 2] * f2[(size_t)sidx[p * 3 + 2] * C2_ + t];
            xc[(size_t)p * CIN_] = to_tf32(acc);
        }
    } else {
        // skip transpose: [C1][N1] -> xcat[...][256+c]
        int r  = blk - 4096;                 // 0 .. 8191
        int b  = r >> 10;
        int rem = r & 1023;
        int c0 = (rem >> 8) * 32;            // 0..3 -> 0..96
        int n0 = (rem & 255) * 32;
        int tx = t & 31, ty = t >> 5;
        const float* src = f1 + (size_t)b * C1_ * N1_;
#pragma unroll
        for (int i = 0; i < 32; i += 8)
            tile[ty + i][tx] = src[(size_t)(c0 + ty + i) * N1_ + n0 + tx];
        __syncthreads();
        float* dst = g_xcat + (size_t)b * N1_ * CIN_;
#pragma unroll
        for (int i = 0; i < 32; i += 8)
            dst[(size_t)(n0 + ty + i) * CIN_ + C2_ + c0 + tx] = to_tf32(tile[tx][ty + i]);
    }
}

// ---------------- 6) fused 2-layer MLP via mma.sync tf32 -------------------
// Block: 128 points x 256 out-channels (full H). Phase 1: y = relu(W1.x+c1)
// accumulated in regs, written tf32 into SMEM in phase-2 A-fragment order.
// Phase 2: out = relu(W2.y+c2) streamed from SMEM yfrag + W2 staging.
// SMEM: [0, 49152) phase1 double buffers (A 8KB + B 16KB each; phase2 reuses
//        first 32KB for W2 double buffers), [49152, 180224) yfrag 128KB.
#define P1_BUF_FLOATS 6144
#define YFRAG_OFF     12288          // floats
#define MLP_SMEM      180224

__global__ void __launch_bounds__(256)
mlp_fused_kernel(float* __restrict__ out_final) {
    extern __shared__ float smem[];
    uint32_t sbase = smem_u32(smem);

    int tid  = threadIdx.x;
    int wid  = tid >> 5;
    int lane = tid & 31;
    int g    = lane >> 2;        // groupID 0..7
    int t4   = lane & 3;         // threadID_in_group

    int wm = wid & 1;            // 0..1  (M warps)
    int wn = wid >> 1;           // 0..3  (N warps)

    int bz = blockIdx.x >> 6;
    int m0 = (blockIdx.x & 63) * 128;

    const float* Abase = g_xcat + ((size_t)(bz * N1_ + m0)) * CIN_;
    float* yf = smem + YFRAG_OFF;

    float acc[4][8][4] = {};

    // ---- phase-1 staging macro (A from xcat, B from W1) ----
#define STAGE1(buf, kt) do {                                                   \
    uint32_t dbase = sbase + (buf) * (P1_BUF_FLOATS * 4);                      \
    _Pragma("unroll")                                                          \
    for (int c = 0; c < 2; c++) {                                              \
        int id = tid + c * 256;                                                \
        int m = id >> 2, c4 = id & 3;                                          \
        int r = m & 15;                                                        \
        int off = (((m >> 4) * 2 + (c4 >> 1)) * 4 + 2 * (c4 & 1) + (r >> 3)) * 32 \
                  + (r & 7) * 4;                                               \
        cpa16(dbase + off * 4, Abase + (size_t)m * CIN_ + (kt) * 16 + c4 * 4); \
    }                                                                          \
    _Pragma("unroll")                                                          \
    for (int c = 0; c < 4; c++) {                                              \
        int id = tid + c * 256;                                                \
        int n = id >> 2, c4 = id & 3;                                          \
        int off = 2048 + (((n >> 3) * 2 + (c4 >> 1)) * 2 + (c4 & 1)) * 32      \
                  + (n & 7) * 4;                                               \
        cpa16(dbase + off * 4, g_A1 + (size_t)n * CIN_ + (kt) * 16 + c4 * 4);  \
    }                                                                          \
    CP_COMMIT();                                                               \
} while (0)

    // ---- phase-2 B staging (W2 fragments into reused low SMEM) ----
#define STAGE2B(buf, kt) do {                                                  \
    uint32_t dbase = sbase + (buf) * 16384;                                    \
    _Pragma("unroll")                                                          \
    for (int c = 0; c < 4; c++) {                                              \
        int id = tid + c * 256;                                                \
        int n = id >> 2, c4 = id & 3;                                          \
        int off = (((n >> 3) * 2 + (c4 >> 1)) * 2 + (c4 & 1)) * 32             \
                  + (n & 7) * 4;                                               \
        cpa16(dbase + off * 4, g_A2 + (size_t)n * H_ + (kt) * 16 + c4 * 4);    \
    }                                                                          \
    CP_COMMIT();                                                               \
} while (0)

    // ================= phase 1: K = 384 =================
    STAGE1(0, 0);
#pragma unroll 1
    for (int kt = 0; kt < CIN_ / 16; kt++) {
        int cur = kt & 1;
        if (kt + 1 < CIN_ / 16) { STAGE1(cur ^ 1, kt + 1); CP_WAIT1(); }
        else                    { CP_WAIT0(); }
        __syncthreads();
        const float* As = smem + cur * P1_BUF_FLOATS;
        const float* Bs = As + 2048;
#pragma unroll
        for (int ks = 0; ks < 2; ks++) {
            uint32_t a[4][4];
#pragma unroll
            for (int mi = 0; mi < 4; mi++) {
                const float* ap = As + (((wm * 4 + mi) * 2 + ks) * 4) * 32 + lane;
                a[mi][0] = __float_as_uint(ap[0]);
                a[mi][1] = __float_as_uint(ap[32]);
                a[mi][2] = __float_as_uint(ap[64]);
                a[mi][3] = __float_as_uint(ap[96]);
            }
#pragma unroll
            for (int ni = 0; ni < 8; ni++) {
                const float* bp = Bs + (((wn * 8 + ni) * 2 + ks) * 2) * 32 + lane;
                uint32_t b0 = __float_as_uint(bp[0]);
                uint32_t b1 = __float_as_uint(bp[32]);
#pragma unroll
                for (int mi = 0; mi < 4; mi++)
                    mma_tf32(acc[mi][ni], a[mi], b0, b1);
            }
        }
        __syncthreads();
    }

    // ---- epilogue 1: bias+relu+tf32 -> yfrag (phase-2 A-fragment order) ----
#pragma unroll
    for (int ni = 0; ni < 8; ni++) {
        int nb = wn * 64 + ni * 8 + 2 * t4;
        float bv0 = __ldg(&g_c1[nb]);
        float bv1 = __ldg(&g_c1[nb + 1]);
#pragma unroll
        for (int mi = 0; mi < 4; mi++) {
            int mt2 = wm * 4 + mi;
            int ksg = wn * 8 + ni;
#pragma unroll
            for (int j = 0; j < 4; j++) {
                float v = to_tf32(fmaxf(acc[mi][ni][j] + ((j & 1) ? bv1 : bv0), 0.0f));
                int reg = 2 * (t4 >> 1) + (j >> 1);
                int ln  = g * 4 + ((2 * t4 + (j & 1)) & 3);
                yf[((mt2 * 32 + ksg) * 4 + reg) * 32 + ln] = v;
            }
        }
    }

    // re-zero accumulators for phase 2
#pragma unroll
    for (int mi = 0; mi < 4; mi++)
#pragma unroll
        for (int ni = 0; ni < 8; ni++)
#pragma unroll
            for (int j = 0; j < 4; j++) acc[mi][ni][j] = 0.0f;

    STAGE2B(0, 0);
    __syncthreads();   // yfrag visible to all

    // ================= phase 2: K = 256 (A resident in SMEM) =================
#pragma unroll 1
    for (int kt = 0; kt < H_ / 16; kt++) {
        int cur = kt & 1;
        if (kt + 1 < H_ / 16) { STAGE2B(cur ^ 1, kt + 1); CP_WAIT1(); }
        else                  { CP_WAIT0(); }
        __syncthreads();
        const float* Bs = smem + cur * 4096;
#pragma unroll
        for (int ks = 0; ks < 2; ks++) {
            uint32_t a[4][4];
#pragma unroll
            for (int mi = 0; mi < 4; mi++) {
                const float* ap = yf + (((wm * 4 + mi) * 32 + kt * 2 + ks) * 4) * 32 + lane;
                a[mi][0] = __float_as_uint(ap[0]);
                a[mi][1] = __float_as_uint(ap[32]);
                a[mi][2] = __float_as_uint(ap[64]);
                a[mi][3] = __float_as_uint(ap[96]);
            }
#pragma unroll
            for (int ni = 0; ni < 8; ni++) {
                const float* bp = Bs + (((wn * 8 + ni) * 2 + ks) * 2) * 32 + lane;
                uint32_t b0 = __float_as_uint(bp[0]);
                uint32_t b1 = __float_as_uint(bp[32]);
#pragma unroll
                for (int mi = 0; mi < 4; mi++)
                    mma_tf32(acc[mi][ni], a[mi], b0, b1);
            }
        }
        __syncthreads();
    }

    // ---- epilogue 2: bias+relu -> out [B][H][N1] (coalesced along points) ----
    float* dst = out_final + (size_t)bz * H_ * N1_;
#pragma unroll
    for (int ni = 0; ni < 8; ni++) {
        int n = wn * 64 + ni * 8 + 2 * t4;
        float bv0 = __ldg(&g_c2[n]);
        float bv1 = __ldg(&g_c2[n + 1]);
#pragma unroll
        for (int mi = 0; mi < 4; mi++) {
            int m = m0 + wm * 64 + mi * 16 + g;
            float c0 = fmaxf(acc[mi][ni][0] + bv0, 0.0f);
            float c1 = fmaxf(acc[mi][ni][1] + bv1, 0.0f);
            float c2 = fmaxf(acc[mi][ni][2] + bv0, 0.0f);
            float c3 = fmaxf(acc[mi][ni][3] + bv1, 0.0f);
            dst[(size_t)n * N1_ + m]           = c0;
            dst[(size_t)(n + 1) * N1_ + m]     = c1;
            dst[(size_t)n * N1_ + m + 8]       = c2;
            dst[(size_t)(n + 1) * N1_ + m + 8] = c3;
        }
    }
}

// ---------------- launch ----------------------------------------------------
extern "C" void kernel_launch(void* const* d_in, const int* in_sizes, int n_in,
                              void* d_out, int out_size) {
    const float* xyz1      = (const float*)d_in[0];
    const float* xyz2      = (const float*)d_in[1];
    const float* features1 = (const float*)d_in[2];
    const float* features2 = (const float*)d_in[3];
    const float* w1 = (const float*)d_in[4];
    const float* b1 = (const float*)d_in[5];
    const float* g1 = (const float*)d_in[6];
    const float* be1 = (const float*)d_in[7];
    const float* m1 = (const float*)d_in[8];
    const float* v1 = (const float*)d_in[9];
    const float* w2 = (const float*)d_in[10];
    const float* b2 = (const float*)d_in[11];
    const float* g2 = (const float*)d_in[12];
    const float* be2 = (const float*)d_in[13];
    const float* m2 = (const float*)d_in[14];
    const float* v2 = (const float*)d_in[15];
    float* out = (float*)d_out;

    cudaFuncSetAttribute(mlp_fused_kernel,
                         cudaFuncAttributeMaxDynamicSharedMemorySize, MLP_SMEM);

    transpose_f2_kernel<<<dim3(N2_ / 32, C2_ / 32, B_), dim3(32, 8)>>>(features2);
    setup_kernel<<<96, 256>>>(xyz2, w1, b1, g1, be1, m1, v1,
                              w2, b2, g2, be2, m2, v2);
    knn_part_kernel<<<dim3(N1_ / 256, 4, B_), 128>>>(xyz1);
    knn_merge_kernel<<<(B_ * N1_) / 256, 256>>>(xyz1);
    interp_skip_kernel<<<4096 + 8192, 256>>>(features1);
    mlp_fused_kernel<<<512, 256, MLP_SMEM>>>(out);
}